// round 16
// baseline (speedup 1.0000x reference)
#include <cuda_runtime.h>
#include <cuda_fp16.h>
#include <cstdint>
#include <math.h>

// ============================================================================
// BinaryLinear: y[8192,4096] = x[8192,4096] @ (aa*tanh(kk*W))^T + bias
// fp16 mma.sync.m16n8k16 register GEMM (fp32 acc), ldmatrix.x4, frag dbl-buffer,
// cross-stage kq0 preload (zero post-barrier LDSM head).
// R16: CTA 128x256, 8 warps (2x4), 1 CTA/SM -> fewer LDGSTS/warp, -25% L2.
// 3-stage cp.async, TK=64 halves, SW128 swizzle, stage rotation, R12 ordering.
// ============================================================================

#define MDIM 8192
#define NDIM 4096
#define KDIM 4096

#define TM 128
#define TN 256
#define TK 64                          // halves per stage-row (128B)
#define NSTAGES 3
#define KITERS (KDIM / TK)             // 64

#define A_STAGE_BYTES (TM * TK * 2)    // 16384
#define B_STAGE_BYTES (TN * TK * 2)    // 32768
#define STAGE_BYTES (A_STAGE_BYTES + B_STAGE_BYTES)     // 49152
#define SMEM_BYTES (NSTAGES * STAGE_BYTES)              // 147456

#define W_PREP_BLOCKS (NDIM * KDIM / 4096)   // 4096 (16 elems/thread)
#define X_PREP_BLOCKS (MDIM * KDIM / 4096)   // 8192

// fp16 operands (persistent scratch)
__device__ __half g_wh[NDIM * KDIM];   // fp16(aa*tanh(kk*W))
__device__ __half g_xh[MDIM * KDIM];   // fp16(x)

// ---------------------------------------------------------------------------
__device__ __forceinline__ uint32_t smem_u32(const void* p) {
    uint32_t a;
    asm("{ .reg .u64 t; cvta.to.shared.u64 t, %1; cvt.u32.u64 %0, t; }" : "=r"(a) : "l"(p));
    return a;
}

__device__ __forceinline__ void cp_async16(uint32_t smem_dst, const void* gmem_src) {
    asm volatile("cp.async.cg.shared.global [%0], [%1], 16;" :: "r"(smem_dst), "l"(gmem_src));
}
#define CP_COMMIT() asm volatile("cp.async.commit_group;" ::: "memory")
#define CP_WAIT(n)  asm volatile("cp.async.wait_group %0;" :: "n"(n) : "memory")

__device__ __forceinline__ void ldmatrix_x4(uint32_t& r0, uint32_t& r1,
                                            uint32_t& r2, uint32_t& r3, uint32_t addr) {
    asm volatile("ldmatrix.sync.aligned.m8n8.x4.shared.b16 {%0,%1,%2,%3}, [%4];"
                 : "=r"(r0), "=r"(r1), "=r"(r2), "=r"(r3) : "r"(addr));
}

__device__ __forceinline__ void mma_f16(float d[4], const uint32_t a[4],
                                        const uint32_t b[2], const float c[4]) {
    asm volatile(
        "mma.sync.aligned.m16n8k16.row.col.f32.f16.f16.f32 "
        "{%0,%1,%2,%3}, {%4,%5,%6,%7}, {%8,%9}, {%10,%11,%12,%13};"
        : "=f"(d[0]), "=f"(d[1]), "=f"(d[2]), "=f"(d[3])
        : "r"(a[0]), "r"(a[1]), "r"(a[2]), "r"(a[3]),
          "r"(b[0]), "r"(b[1]),
          "f"(c[0]), "f"(c[1]), "f"(c[2]), "f"(c[3]));
}

// ---------------------------------------------------------------------------
// Fused prep: blocks [0, W_PREP_BLOCKS) convert W (tanh.approx), the rest X.
// ---------------------------------------------------------------------------
__device__ __forceinline__ uint32_t pack2(float lo, float hi) {
    __half2 h = __floats2half2_rn(lo, hi);
    return *reinterpret_cast<uint32_t*>(&h);
}

__device__ __forceinline__ float tanh_fast(float v) {
    float r;
    asm("tanh.approx.f32 %0, %1;" : "=f"(r) : "f"(v));
    return r;
}

__global__ void __launch_bounds__(256) prep_all(const float4* __restrict__ w,
                                                const float4* __restrict__ x,
                                                const float* __restrict__ kk,
                                                const float* __restrict__ aa) {
    if (blockIdx.x < W_PREP_BLOCKS) {
        int i = blockIdx.x * 256 + threadIdx.x;
        float k = *kk, a = *aa;
        float4 v0 = w[4 * i], v1 = w[4 * i + 1], v2 = w[4 * i + 2], v3 = w[4 * i + 3];
        uint4 o0, o1;
        o0.x = pack2(a * tanh_fast(k * v0.x), a * tanh_fast(k * v0.y));
        o0.y = pack2(a * tanh_fast(k * v0.z), a * tanh_fast(k * v0.w));
        o0.z = pack2(a * tanh_fast(k * v1.x), a * tanh_fast(k * v1.y));
        o0.w = pack2(a * tanh_fast(k * v1.z), a * tanh_fast(k * v1.w));
        o1.x = pack2(a * tanh_fast(k * v2.x), a * tanh_fast(k * v2.y));
        o1.y = pack2(a * tanh_fast(k * v2.z), a * tanh_fast(k * v2.w));
        o1.z = pack2(a * tanh_fast(k * v3.x), a * tanh_fast(k * v3.y));
        o1.w = pack2(a * tanh_fast(k * v3.z), a * tanh_fast(k * v3.w));
        reinterpret_cast<uint4*>(g_wh)[2 * i] = o0;
        reinterpret_cast<uint4*>(g_wh)[2 * i + 1] = o1;
    } else {
        int i = (blockIdx.x - W_PREP_BLOCKS) * 256 + threadIdx.x;
        float4 v0 = x[4 * i], v1 = x[4 * i + 1], v2 = x[4 * i + 2], v3 = x[4 * i + 3];
        uint4 o0, o1;
        o0.x = pack2(v0.x, v0.y);  o0.y = pack2(v0.z, v0.w);
        o0.z = pack2(v1.x, v1.y);  o0.w = pack2(v1.z, v1.w);
        o1.x = pack2(v2.x, v2.y);  o1.y = pack2(v2.z, v2.w);
        o1.z = pack2(v3.x, v3.y);  o1.w = pack2(v3.z, v3.w);
        reinterpret_cast<uint4*>(g_xh)[2 * i] = o0;
        reinterpret_cast<uint4*>(g_xh)[2 * i + 1] = o1;
    }
}

// ---------------------------------------------------------------------------
// SMEM: rows of 64 halves (128B = 8 x 16B granules), SW128 swizzle:
// granule c of row r stored at slot (c ^ (r&7)).
// Load one 64-K stage: A 128x64h (1024 granules) + B 256x64h (2048 granules),
// 256 threads -> A: 4/thread, B: 8/thread.
// ---------------------------------------------------------------------------
__device__ __forceinline__ void load_stage(const __half* __restrict__ xh,
                                           const __half* __restrict__ wh,
                                           int m0, int n0, int k0,
                                           uint32_t sdst, int tid) {
#pragma unroll
    for (int i = 0; i < 4; i++) {                 // A: 1024 granules
        int g = tid + i * 256;
        int row = g >> 3, c = g & 7;
        cp_async16(sdst + row * 128 + ((c ^ (row & 7)) << 4),
                   xh + (size_t)(m0 + row) * KDIM + k0 + c * 8);
    }
#pragma unroll
    for (int i = 0; i < 8; i++) {                 // B: 2048 granules
        int g = tid + i * 256;
        int row = g >> 3, c = g & 7;
        cp_async16(sdst + A_STAGE_BYTES + row * 128 + ((c ^ (row & 7)) << 4),
                   wh + (size_t)(n0 + row) * KDIM + k0 + c * 8);
    }
}

// ---------------------------------------------------------------------------
// GEMM: 8 warps (2x4), warp tile 64x64 (4 x 8 of m16n8k16), frag dbl-buffer
// with cross-stage kq0 preload. 1 CTA/SM.
// ---------------------------------------------------------------------------
__global__ void __launch_bounds__(256, 1) gemm_kernel(const float* __restrict__ bias,
                                                      float* __restrict__ out) {
    extern __shared__ char smem_raw[];
    const uint32_t sbase = smem_u32(smem_raw);

    const int tid = threadIdx.x;
    const int wid = tid >> 5;
    const int lane = tid & 31;
    const int wm = wid >> 2;          // 0..1 -> 64-row slab
    const int wn = wid & 3;           // 0..3 -> 64-col slab
    const int lr = lane >> 2;         // 0..7
    const int lc = lane & 3;          // 0..3

    // ldmatrix lane decomposition
    const int i8 = lane & 7;
    const int sel = lane >> 3;
    const int a_msel = (sel & 1) << 3;
    const int a_gsel = sel >> 1;
    const int b_nsel = (sel >> 1) << 3;
    const int b_gsel = sel & 1;
    const uint32_t aRowOff = (uint32_t)(wm * 64 + a_msel + i8) * 128;
    const uint32_t bRowOff = (uint32_t)(wn * 64 + b_nsel + i8) * 128;

    // grouped tile swizzle: 64 m-tiles x 16 n-tiles, GROUP_M = 8
    const int pid = blockIdx.x;
    const int group = pid >> 7;                   // / (8*16)
    const int rem = pid & 127;
    const int pm = (group << 3) + (rem & 7);
    const int pn = rem >> 3;
    const int m0 = pm * TM;
    const int n0 = pn * TN;

    float acc[4][8][4];
#pragma unroll
    for (int i = 0; i < 4; i++)
#pragma unroll
        for (int j = 0; j < 8; j++) {
            acc[i][j][0] = 0.f; acc[i][j][1] = 0.f;
            acc[i][j][2] = 0.f; acc[i][j][3] = 0.f;
        }

    // prologue: fill stages 0,1
#pragma unroll
    for (int s = 0; s < NSTAGES - 1; s++) {
        load_stage(g_xh, g_wh, m0, n0, s * TK, sbase + s * STAGE_BYTES, tid);
        CP_COMMIT();
    }

    uint32_t af[2][4][4];
    uint32_t bf[2][8][2];

    // preload kq0 frags of stage 0 (before mainloop)
    CP_WAIT(1);                  // stage 0 resident
    __syncthreads();
    {
        const uint32_t aB = sbase, bB = sbase + A_STAGE_BYTES;
        const int ga = a_gsel, gb = b_gsel;
#pragma unroll
        for (int ms = 0; ms < 4; ms++)
            ldmatrix_x4(af[0][ms][0], af[0][ms][1], af[0][ms][2], af[0][ms][3],
                        aB + aRowOff + ms * 2048 + ((ga ^ i8) << 4));
#pragma unroll
        for (int nsp = 0; nsp < 4; nsp++)
            ldmatrix_x4(bf[0][2 * nsp][0], bf[0][2 * nsp][1],
                        bf[0][2 * nsp + 1][0], bf[0][2 * nsp + 1][1],
                        bB + bRowOff + nsp * 2048 + ((gb ^ i8) << 4));
    }

    uint32_t curBase = sbase;                         // stage being consumed
    uint32_t ldBase = sbase + 2 * STAGE_BYTES;        // stage being loaded
    const uint32_t sEnd = sbase + NSTAGES * STAGE_BYTES;

    for (int it = 0; it < KITERS; ++it) {
        CP_WAIT(0);              // stages it AND it+1 resident
        __syncthreads();

        const uint32_t aBase = curBase;
        const uint32_t bBase = curBase + A_STAGE_BYTES;
        uint32_t nBase = curBase + STAGE_BYTES;
        if (nBase == sEnd) nBase = sbase;             // stage it+1 slot

        // front-batched gmem burst for stage it+2 (R12 ordering, frozen)
        const int jt = it + NSTAGES - 1;
        if (jt < KITERS)
            load_stage(g_xh, g_wh, m0, n0, jt * TK, ldBase, tid);
        CP_COMMIT();             // always commit: CP_WAIT(0) handles the rest

#pragma unroll
        for (int kq = 0; kq < 4; kq++) {          // 4 x k16 steps
            const int cur = kq & 1, nxt = cur ^ 1;
            if (kq < 3) {                         // prefetch kq+1 frags (this stage)
                const int ga = 2 * (kq + 1) + a_gsel;
                const int gb = 2 * (kq + 1) + b_gsel;
#pragma unroll
                for (int ms = 0; ms < 4; ms++)
                    ldmatrix_x4(af[nxt][ms][0], af[nxt][ms][1],
                                af[nxt][ms][2], af[nxt][ms][3],
                                aBase + aRowOff + ms * 2048 + ((ga ^ i8) << 4));
#pragma unroll
                for (int nsp = 0; nsp < 4; nsp++)
                    ldmatrix_x4(bf[nxt][2 * nsp][0], bf[nxt][2 * nsp][1],
                                bf[nxt][2 * nsp + 1][0], bf[nxt][2 * nsp + 1][1],
                                bBase + bRowOff + nsp * 2048 + ((gb ^ i8) << 4));
            } else {                              // kq==3: preload NEXT stage's kq0
                const int ga = a_gsel, gb = b_gsel;
                const uint32_t aN = nBase, bN = nBase + A_STAGE_BYTES;
#pragma unroll
                for (int ms = 0; ms < 4; ms++)
                    ldmatrix_x4(af[nxt][ms][0], af[nxt][ms][1],
                                af[nxt][ms][2], af[nxt][ms][3],
                                aN + aRowOff + ms * 2048 + ((ga ^ i8) << 4));
#pragma unroll
                for (int nsp = 0; nsp < 4; nsp++)
                    ldmatrix_x4(bf[nxt][2 * nsp][0], bf[nxt][2 * nsp][1],
                                bf[nxt][2 * nsp + 1][0], bf[nxt][2 * nsp + 1][1],
                                bN + bRowOff + nsp * 2048 + ((gb ^ i8) << 4));
            }
#pragma unroll
            for (int ms = 0; ms < 4; ms++)
#pragma unroll
                for (int ns = 0; ns < 8; ns++)
                    mma_f16(acc[ms][ns], af[cur][ms], bf[cur][ns], acc[ms][ns]);
        }

        // rotate stage bases (no modulo)
        curBase += STAGE_BYTES;  if (curBase == sEnd) curBase = sbase;
        ldBase  += STAGE_BYTES;  if (ldBase  == sEnd) ldBase  = sbase;
    }

    // epilogue: c0,c1 at (row, 2*lc), c2,c3 at (row+8, 2*lc)
#pragma unroll
    for (int ms = 0; ms < 4; ms++) {
        const int rg = m0 + wm * 64 + ms * 16 + lr;
        float* o0 = out + (size_t)rg * NDIM;
        float* o1 = out + (size_t)(rg + 8) * NDIM;
#pragma unroll
        for (int ns = 0; ns < 8; ns++) {
            const int cg = n0 + wn * 64 + ns * 8 + 2 * lc;
            const float2 bv = *reinterpret_cast<const float2*>(bias + cg);
            float2 v0, v1;
            v0.x = acc[ms][ns][0] + bv.x;  v0.y = acc[ms][ns][1] + bv.y;
            v1.x = acc[ms][ns][2] + bv.x;  v1.y = acc[ms][ns][3] + bv.y;
            *reinterpret_cast<float2*>(o0 + cg) = v0;
            *reinterpret_cast<float2*>(o1 + cg) = v1;
        }
    }
}

// ---------------------------------------------------------------------------
extern "C" void kernel_launch(void* const* d_in, const int* in_sizes, int n_in,
                              void* d_out, int out_size) {
    const float* x = (const float*)d_in[0];      // [4,2048,4096]
    const float* w = (const float*)d_in[1];      // [4096,4096]
    const float* bias = (const float*)d_in[2];   // [4096]
    const float* kk = (const float*)d_in[3];
    const float* aa = (const float*)d_in[4];
    float* out = (float*)d_out;                  // [4,2048,4096]

    prep_all<<<W_PREP_BLOCKS + X_PREP_BLOCKS, 256>>>((const float4*)w,
                                                     (const float4*)x, kk, aa);

    cudaFuncSetAttribute(gemm_kernel, cudaFuncAttributeMaxDynamicSharedMemorySize, SMEM_BYTES);
    gemm_kernel<<<(MDIM / TM) * (NDIM / TN), 256, SMEM_BYTES>>>(bias, out);
}

// round 17
// speedup vs baseline: 1.0269x; 1.0269x over previous
#include <cuda_runtime.h>
#include <cuda.h>
#include <cuda_fp16.h>
#include <cstdint>
#include <math.h>

// ============================================================================
// BinaryLinear: y[8192,4096] = x[8192,4096] @ (aa*tanh(kk*W))^T + bias
// fp16 mma.sync.m16n8k16 register GEMM (fp32 acc), ldmatrix.x4, frag dbl-buffer,
// cross-stage kq0 preload. CTA 128x128, 4 warps, 2 CTAs/SM, 3 stages, TK=64.
// R17: TMA (cp.async.bulk.tensor.2d, HW SW128 swizzle) + full/empty mbarriers
//      replace cp.async + __syncthreads -> warps decoupled, zero LDGSTS issue.
// ============================================================================

#define MDIM 8192
#define NDIM 4096
#define KDIM 4096

#define TM 128
#define TN 128
#define TK 64                          // halves per stage-row (128B)
#define NSTAGES 3
#define KITERS (KDIM / TK)             // 64

#define A_STAGE_BYTES (TM * TK * 2)    // 16384
#define B_STAGE_BYTES (TN * TK * 2)    // 16384
#define STAGE_BYTES (A_STAGE_BYTES + B_STAGE_BYTES)     // 32768
#define SMEM_BYTES (1024 + NSTAGES * STAGE_BYTES + 1024)  // pad + stages + align

#define W_PREP_BLOCKS (NDIM * KDIM / 4096)   // 4096 (16 elems/thread)
#define X_PREP_BLOCKS (MDIM * KDIM / 4096)   // 8192

// fp16 operands (persistent scratch), 1KB-aligned for TMA
__device__ __align__(1024) __half g_wh[NDIM * KDIM];
__device__ __align__(1024) __half g_xh[MDIM * KDIM];

// ---------------------------------------------------------------------------
__device__ __forceinline__ uint32_t smem_u32(const void* p) {
    uint32_t a;
    asm("{ .reg .u64 t; cvta.to.shared.u64 t, %1; cvt.u32.u64 %0, t; }" : "=r"(a) : "l"(p));
    return a;
}

#define MBARRIER_INIT(addr, cnt) \
    asm volatile("mbarrier.init.shared.b64 [%0], %1;" :: "r"(addr), "r"(cnt) : "memory")
#define MBARRIER_EXPECT_TX(addr, bytes) \
    asm volatile("mbarrier.arrive.expect_tx.shared.b64 _, [%0], %1;" \
                 :: "r"(addr), "r"(bytes) : "memory")
#define MBARRIER_ARRIVE(addr) \
    asm volatile("mbarrier.arrive.shared.b64 _, [%0];" :: "r"(addr) : "memory")

#define MBARRIER_WAIT_PARITY(addr, parity) do {                                   \
    uint32_t _mb = (addr); uint32_t _ph = (parity); uint32_t _ok;                 \
    asm volatile("{ .reg .pred p;"                                               \
        " mbarrier.try_wait.parity.acquire.cta.shared::cta.b64 p, [%1], %2;"      \
        " selp.b32 %0, 1, 0, p; }" : "=r"(_ok) : "r"(_mb), "r"(_ph) : "memory");  \
    if (!_ok) {                                                                   \
        asm volatile("{ .reg .pred P1;"                                          \
            "W_%=: mbarrier.try_wait.parity.acquire.cta.shared::cta.b64 P1, [%0], %1, 0x989680;" \
            " @P1 bra.uni D_%=;  bra.uni W_%=;  D_%=: }"                           \
            :: "r"(_mb), "r"(_ph) : "memory");                                    \
    } } while (0)

#define TMA_LOAD_2D(dst, tmap, x, y, mbar) \
    asm volatile("cp.async.bulk.tensor.2d.shared::cta.global.tile.mbarrier::complete_tx::bytes " \
                 "[%0], [%1, {%2, %3}], [%4];" \
                 :: "r"(dst), "l"(tmap), "r"(x), "r"(y), "r"(mbar) : "memory")

__device__ __forceinline__ void ldmatrix_x4(uint32_t& r0, uint32_t& r1,
                                            uint32_t& r2, uint32_t& r3, uint32_t addr) {
    asm volatile("ldmatrix.sync.aligned.m8n8.x4.shared.b16 {%0,%1,%2,%3}, [%4];"
                 : "=r"(r0), "=r"(r1), "=r"(r2), "=r"(r3) : "r"(addr));
}

__device__ __forceinline__ void mma_f16(float d[4], const uint32_t a[4],
                                        const uint32_t b[2], const float c[4]) {
    asm volatile(
        "mma.sync.aligned.m16n8k16.row.col.f32.f16.f16.f32 "
        "{%0,%1,%2,%3}, {%4,%5,%6,%7}, {%8,%9}, {%10,%11,%12,%13};"
        : "=f"(d[0]), "=f"(d[1]), "=f"(d[2]), "=f"(d[3])
        : "r"(a[0]), "r"(a[1]), "r"(a[2]), "r"(a[3]),
          "r"(b[0]), "r"(b[1]),
          "f"(c[0]), "f"(c[1]), "f"(c[2]), "f"(c[3]));
}

// ---------------------------------------------------------------------------
// Fused prep: blocks [0, W_PREP_BLOCKS) convert W (tanh.approx), the rest X.
// ---------------------------------------------------------------------------
__device__ __forceinline__ uint32_t pack2(float lo, float hi) {
    __half2 h = __floats2half2_rn(lo, hi);
    return *reinterpret_cast<uint32_t*>(&h);
}

__device__ __forceinline__ float tanh_fast(float v) {
    float r;
    asm("tanh.approx.f32 %0, %1;" : "=f"(r) : "f"(v));
    return r;
}

__global__ void __launch_bounds__(256) prep_all(const float4* __restrict__ w,
                                                const float4* __restrict__ x,
                                                const float* __restrict__ kk,
                                                const float* __restrict__ aa) {
    if (blockIdx.x < W_PREP_BLOCKS) {
        int i = blockIdx.x * 256 + threadIdx.x;
        float k = *kk, a = *aa;
        float4 v0 = w[4 * i], v1 = w[4 * i + 1], v2 = w[4 * i + 2], v3 = w[4 * i + 3];
        uint4 o0, o1;
        o0.x = pack2(a * tanh_fast(k * v0.x), a * tanh_fast(k * v0.y));
        o0.y = pack2(a * tanh_fast(k * v0.z), a * tanh_fast(k * v0.w));
        o0.z = pack2(a * tanh_fast(k * v1.x), a * tanh_fast(k * v1.y));
        o0.w = pack2(a * tanh_fast(k * v1.z), a * tanh_fast(k * v1.w));
        o1.x = pack2(a * tanh_fast(k * v2.x), a * tanh_fast(k * v2.y));
        o1.y = pack2(a * tanh_fast(k * v2.z), a * tanh_fast(k * v2.w));
        o1.z = pack2(a * tanh_fast(k * v3.x), a * tanh_fast(k * v3.y));
        o1.w = pack2(a * tanh_fast(k * v3.z), a * tanh_fast(k * v3.w));
        reinterpret_cast<uint4*>(g_wh)[2 * i] = o0;
        reinterpret_cast<uint4*>(g_wh)[2 * i + 1] = o1;
    } else {
        int i = (blockIdx.x - W_PREP_BLOCKS) * 256 + threadIdx.x;
        float4 v0 = x[4 * i], v1 = x[4 * i + 1], v2 = x[4 * i + 2], v3 = x[4 * i + 3];
        uint4 o0, o1;
        o0.x = pack2(v0.x, v0.y);  o0.y = pack2(v0.z, v0.w);
        o0.z = pack2(v1.x, v1.y);  o0.w = pack2(v1.z, v1.w);
        o1.x = pack2(v2.x, v2.y);  o1.y = pack2(v2.z, v2.w);
        o1.z = pack2(v3.x, v3.y);  o1.w = pack2(v3.z, v3.w);
        reinterpret_cast<uint4*>(g_xh)[2 * i] = o0;
        reinterpret_cast<uint4*>(g_xh)[2 * i + 1] = o1;
    }
}

// ---------------------------------------------------------------------------
// GEMM: 4 warps (2x2), warp tile 64x64, frag dbl-buffer + cross-stage preload.
// TMA-fed, mbarrier-synchronized (no __syncthreads in mainloop).
// SMEM stage layout = TMA SW128 = rows of 128B, granule c at slot c^(r&7)
// (identical to previous manual swizzle; ldmatrix addressing unchanged).
// ---------------------------------------------------------------------------
__global__ void __launch_bounds__(128, 2) gemm_kernel(
        const __grid_constant__ CUtensorMap tmA,
        const __grid_constant__ CUtensorMap tmB,
        const float* __restrict__ bias,
        float* __restrict__ out) {
    extern __shared__ char smem_raw[];
    const uint32_t s0 = (smem_u32(smem_raw) + 1023u) & ~1023u;
    const uint32_t FULL = s0;            // full[i]  at s0 + 8*i
    const uint32_t EMPTY = s0 + 24;      // empty[i] at s0 + 24 + 8*i
    const uint32_t stageBase = s0 + 1024;

    const int tid = threadIdx.x;
    const int wid = tid >> 5;
    const int lane = tid & 31;
    const int wm = wid >> 1;          // 0..1 -> 64-row slab
    const int wn = wid & 1;           // 0..1 -> 64-col slab
    const int lr = lane >> 2;         // 0..7
    const int lc = lane & 3;          // 0..3

    // ldmatrix lane decomposition
    const int i8 = lane & 7;
    const int sel = lane >> 3;
    const int a_msel = (sel & 1) << 3;
    const int a_gsel = sel >> 1;
    const int b_nsel = (sel >> 1) << 3;
    const int b_gsel = sel & 1;
    const uint32_t aRowOff = (uint32_t)(wm * 64 + a_msel + i8) * 128;
    const uint32_t bRowOff = (uint32_t)(wn * 64 + b_nsel + i8) * 128;

    // grouped tile swizzle: 64 m-tiles x 32 n-tiles, GROUP_M = 8
    const int pid = blockIdx.x;
    const int group = pid >> 8;
    const int rem = pid & 255;
    const int pm = (group << 3) + (rem & 7);
    const int pn = rem >> 3;
    const int m0 = pm * TM;
    const int n0 = pn * TN;

    float acc[4][8][4];
#pragma unroll
    for (int i = 0; i < 4; i++)
#pragma unroll
        for (int j = 0; j < 8; j++) {
            acc[i][j][0] = 0.f; acc[i][j][1] = 0.f;
            acc[i][j][2] = 0.f; acc[i][j][3] = 0.f;
        }

    // init barriers: full count=1 (expect_tx provides arrival), empty count=128
    if (tid == 0) {
#pragma unroll
        for (int i = 0; i < NSTAGES; i++) {
            MBARRIER_INIT(FULL + 8 * i, 1);
            MBARRIER_INIT(EMPTY + 8 * i, 128);
        }
        asm volatile("fence.mbarrier_init.release.cluster;" ::: "memory");
    }
    __syncthreads();

    // prologue: TMA stages 0,1
    if (tid == 0) {
#pragma unroll
        for (int s = 0; s < NSTAGES - 1; s++) {
            const uint32_t dst = stageBase + s * STAGE_BYTES;
            MBARRIER_EXPECT_TX(FULL + 8 * s, STAGE_BYTES);
            TMA_LOAD_2D(dst, &tmA, s * TK, m0, FULL + 8 * s);
            TMA_LOAD_2D(dst + A_STAGE_BYTES, &tmB, s * TK, n0, FULL + 8 * s);
        }
    }

    uint32_t af[2][4][4];
    uint32_t bf[2][8][2];

    // preload kq0 frags of stage 0
    MBARRIER_WAIT_PARITY(FULL + 0, 0);
    {
        const uint32_t aB = stageBase, bB = stageBase + A_STAGE_BYTES;
        const int ga = a_gsel, gb = b_gsel;
#pragma unroll
        for (int ms = 0; ms < 4; ms++)
            ldmatrix_x4(af[0][ms][0], af[0][ms][1], af[0][ms][2], af[0][ms][3],
                        aB + aRowOff + ms * 2048 + ((ga ^ i8) << 4));
#pragma unroll
        for (int nsp = 0; nsp < 4; nsp++)
            ldmatrix_x4(bf[0][2 * nsp][0], bf[0][2 * nsp][1],
                        bf[0][2 * nsp + 1][0], bf[0][2 * nsp + 1][1],
                        bB + bRowOff + nsp * 2048 + ((gb ^ i8) << 4));
    }

    int s0i = 0, p0 = 0;      // cursor: stage it
    int s1i = 1, p1 = 0;      // cursor: stage it+1
    int s2i = 2;              // producer slot for stage it+2

    for (int it = 0; it < KITERS; ++it) {
        MBARRIER_WAIT_PARITY(FULL + 8 * s0i, p0);        // stage it resident

        const uint32_t aBase = stageBase + s0i * STAGE_BYTES;
        const uint32_t bBase = aBase + A_STAGE_BYTES;

        // producer: stage it+2 (tid0 only)
        const int jt = it + 2;
        if (tid == 0 && jt < KITERS) {
            if (jt >= 3) {
                const int ew = ((jt - 3) / 3) & 1;
                MBARRIER_WAIT_PARITY(EMPTY + 8 * s2i, ew);
            }
            const uint32_t dst = stageBase + s2i * STAGE_BYTES;
            MBARRIER_EXPECT_TX(FULL + 8 * s2i, STAGE_BYTES);
            TMA_LOAD_2D(dst, &tmA, jt * TK, m0, FULL + 8 * s2i);
            TMA_LOAD_2D(dst + A_STAGE_BYTES, &tmB, jt * TK, n0, FULL + 8 * s2i);
        }

        // stage it+1 residency (needed by kq3 preload); guarded for last iter
        if (it + 1 < KITERS)
            MBARRIER_WAIT_PARITY(FULL + 8 * s1i, p1);
        const uint32_t nA = stageBase + s1i * STAGE_BYTES;

#pragma unroll
        for (int kq = 0; kq < 4; kq++) {          // 4 x k16 steps
            const int cur = kq & 1, nxt = cur ^ 1;
            if (kq < 3) {                         // prefetch kq+1 frags (this stage)
                const int ga = 2 * (kq + 1) + a_gsel;
                const int gb = 2 * (kq + 1) + b_gsel;
#pragma unroll
                for (int ms = 0; ms < 4; ms++)
                    ldmatrix_x4(af[nxt][ms][0], af[nxt][ms][1],
                                af[nxt][ms][2], af[nxt][ms][3],
                                aBase + aRowOff + ms * 2048 + ((ga ^ i8) << 4));
#pragma unroll
                for (int nsp = 0; nsp < 4; nsp++)
                    ldmatrix_x4(bf[nxt][2 * nsp][0], bf[nxt][2 * nsp][1],
                                bf[nxt][2 * nsp + 1][0], bf[nxt][2 * nsp + 1][1],
                                bBase + bRowOff + nsp * 2048 + ((gb ^ i8) << 4));
            } else {                              // kq==3: preload NEXT stage's kq0
                const int ga = a_gsel, gb = b_gsel;
                const uint32_t bN = nA + A_STAGE_BYTES;
#pragma unroll
                for (int ms = 0; ms < 4; ms++)
                    ldmatrix_x4(af[nxt][ms][0], af[nxt][ms][1],
                                af[nxt][ms][2], af[nxt][ms][3],
                                nA + aRowOff + ms * 2048 + ((ga ^ i8) << 4));
#pragma unroll
                for (int nsp = 0; nsp < 4; nsp++)
                    ldmatrix_x4(bf[nxt][2 * nsp][0], bf[nxt][2 * nsp][1],
                                bf[nxt][2 * nsp + 1][0], bf[nxt][2 * nsp + 1][1],
                                bN + bRowOff + nsp * 2048 + ((gb ^ i8) << 4));
            }
#pragma unroll
            for (int ms = 0; ms < 4; ms++)
#pragma unroll
                for (int ns = 0; ns < 8; ns++)
                    mma_f16(acc[ms][ns], af[cur][ms], bf[cur][ns], acc[ms][ns]);
        }

        // all reads of stage it consumed by kq3's MMA -> release the slot
        MBARRIER_ARRIVE(EMPTY + 8 * s0i);

        s0i++; if (s0i == NSTAGES) { s0i = 0; p0 ^= 1; }
        s1i++; if (s1i == NSTAGES) { s1i = 0; p1 ^= 1; }
        s2i++; if (s2i == NSTAGES) s2i = 0;
    }

    // epilogue: c0,c1 at (row, 2*lc), c2,c3 at (row+8, 2*lc)
#pragma unroll
    for (int ms = 0; ms < 4; ms++) {
        const int rg = m0 + wm * 64 + ms * 16 + lr;
        float* o0 = out + (size_t)rg * NDIM;
        float* o1 = out + (size_t)(rg + 8) * NDIM;
#pragma unroll
        for (int ns = 0; ns < 8; ns++) {
            const int cg = n0 + wn * 64 + ns * 8 + 2 * lc;
            const float2 bv = *reinterpret_cast<const float2*>(bias + cg);
            float2 v0, v1;
            v0.x = acc[ms][ns][0] + bv.x;  v0.y = acc[ms][ns][1] + bv.y;
            v1.x = acc[ms][ns][2] + bv.x;  v1.y = acc[ms][ns][3] + bv.y;
            *reinterpret_cast<float2*>(o0 + cg) = v0;
            *reinterpret_cast<float2*>(o1 + cg) = v1;
        }
    }
}

// ---------------------------------------------------------------------------
// Host: build tensor maps via driver entry point (no -lcuda link dependency).
// ---------------------------------------------------------------------------
typedef CUresult (*EncodeTiledFn)(
    CUtensorMap*, CUtensorMapDataType, cuuint32_t, void*,
    const cuuint64_t*, const cuuint64_t*, const cuuint32_t*, const cuuint32_t*,
    CUtensorMapInterleave, CUtensorMapSwizzle, CUtensorMapL2promotion,
    CUtensorMapFloatOOBfill);

extern "C" void kernel_launch(void* const* d_in, const int* in_sizes, int n_in,
                              void* d_out, int out_size) {
    const float* x = (const float*)d_in[0];      // [4,2048,4096]
    const float* w = (const float*)d_in[1];      // [4096,4096]
    const float* bias = (const float*)d_in[2];   // [4096]
    const float* kk = (const float*)d_in[3];
    const float* aa = (const float*)d_in[4];
    float* out = (float*)d_out;                  // [4,2048,4096]

    prep_all<<<W_PREP_BLOCKS + X_PREP_BLOCKS, 256>>>((const float4*)w,
                                                     (const float4*)x, kk, aa);

    // tensor maps (host-side; deterministic, capture-safe: no stream ops)
    void* pX = nullptr;
    void* pW = nullptr;
    cudaGetSymbolAddress(&pX, g_xh);
    cudaGetSymbolAddress(&pW, g_wh);

    void* fptr = nullptr;
    cudaDriverEntryPointQueryResult qr;
    cudaGetDriverEntryPoint("cuTensorMapEncodeTiled", &fptr,
                            cudaEnableDefault, &qr);
    EncodeTiledFn enc = (EncodeTiledFn)fptr;

    CUtensorMap tmA, tmB;
    {
        cuuint64_t dims[2] = {(cuuint64_t)KDIM, (cuuint64_t)MDIM};
        cuuint64_t strides[1] = {(cuuint64_t)KDIM * 2};
        cuuint32_t box[2] = {TK, TM};                 // 64 x 128 (128B rows)
        cuuint32_t es[2] = {1, 1};
        enc(&tmA, CU_TENSOR_MAP_DATA_TYPE_FLOAT16, 2, pX, dims, strides, box, es,
            CU_TENSOR_MAP_INTERLEAVE_NONE, CU_TENSOR_MAP_SWIZZLE_128B,
            CU_TENSOR_MAP_L2_PROMOTION_L2_128B, CU_TENSOR_MAP_FLOAT_OOB_FILL_NONE);
    }
    {
        cuuint64_t dims[2] = {(cuuint64_t)KDIM, (cuuint64_t)NDIM};
        cuuint64_t strides[1] = {(cuuint64_t)KDIM * 2};
        cuuint32_t box[2] = {TK, TN};                 // 64 x 128
        cuuint32_t es[2] = {1, 1};
        enc(&tmB, CU_TENSOR_MAP_DATA_TYPE_FLOAT16, 2, pW, dims, strides, box, es,
            CU_TENSOR_MAP_INTERLEAVE_NONE, CU_TENSOR_MAP_SWIZZLE_128B,
            CU_TENSOR_MAP_L2_PROMOTION_L2_128B, CU_TENSOR_MAP_FLOAT_OOB_FILL_NONE);
    }

    cudaFuncSetAttribute(gemm_kernel, cudaFuncAttributeMaxDynamicSharedMemorySize, SMEM_BYTES);
    gemm_kernel<<<(MDIM / TM) * (NDIM / TN), 128, SMEM_BYTES>>>(tmA, tmB, bias, out);
}